// round 3
// baseline (speedup 1.0000x reference)
#include <cuda_runtime.h>
#include <math.h>

#define BB 64
#define TT 512
#define HH 768
#define LL 32

// Scratch (static device globals: no allocation allowed)
__device__ float d_em[BB * TT * LL];    // emissions (log domain), 4 MB
__device__ float d_emx[BB * TT * LL];   // exp(emissions), 4 MB
__device__ float d_part[BB];            // per-batch (denom - numer)

// ---- packed f32x2 helpers (Blackwell FFMA2 path, PTX-only) ----
__device__ __forceinline__ unsigned long long pk2(float a, float b) {
    unsigned long long r;
    asm("mov.b64 %0, {%1, %2};" : "=l"(r) : "f"(a), "f"(b));
    return r;
}
__device__ __forceinline__ void upk2(unsigned long long v, float& a, float& b) {
    asm("mov.b64 {%0, %1}, %2;" : "=f"(a), "=f"(b) : "l"(v));
}
__device__ __forceinline__ unsigned long long f2fma(unsigned long long a,
                                                    unsigned long long b,
                                                    unsigned long long c) {
    unsigned long long d;
    asm("fma.rn.f32x2 %0, %1, %2, %3;" : "=l"(d) : "l"(a), "l"(b), "l"(c));
    return d;
}
__device__ __forceinline__ float frcp(float x) {
    float r;
    asm("rcp.approx.f32 %0, %1;" : "=f"(r) : "f"(x));
    return r;
}

// ============================================================
// Kernel 1: emissions = hidden_states @ W + b    (fp32, FFMA2)
// Block tile: 128 rows x 32 cols, 128 threads, thread tile 8x4.
// grid = 256 -> >=2 blocks/SM for latency hiding.
// hsh stored transposed [k][row] so h loads are LDS.128.
// Epilogue writes em and exp(em).
// ============================================================
#define KC 16
__global__ __launch_bounds__(128) void gemm_k(const float* __restrict__ hs,
                                              const float* __restrict__ W,
                                              const float* __restrict__ bias) {
    __shared__ float hsh[KC][128];
    __shared__ float wsh[KC][32];
    const int tid = threadIdx.x;
    const int rowBase = blockIdx.x * 128;
    const int tr = tid >> 3, tc = tid & 7;
    const int r0 = tr * 8, c0 = tc * 4;

    unsigned long long acc[8][2];
    {
        float4 bb = *reinterpret_cast<const float4*>(bias + c0);
#pragma unroll
        for (int r = 0; r < 8; r++) {
            acc[r][0] = pk2(bb.x, bb.y);
            acc[r][1] = pk2(bb.z, bb.w);
        }
    }

    // register prefetch buffers
    float4 hld[4];
    float  wld[4];

    // load chunk 0
#pragma unroll
    for (int i = 0; i < 4; i++) {
        int idx = tid + i * 128;
        int row = idx >> 2, kq = idx & 3;
        hld[i] = *reinterpret_cast<const float4*>(hs + (size_t)(rowBase + row) * HH + kq * 4);
    }
#pragma unroll
    for (int i = 0; i < 4; i++) {
        int idx = tid + i * 128;
        wld[i] = W[(idx >> 5) * LL + (idx & 31)];
    }

    const int NCH = HH / KC;  // 48
    for (int ch = 0; ch < NCH; ch++) {
        __syncthreads();
        // store current chunk to shared (transposed h)
#pragma unroll
        for (int i = 0; i < 4; i++) {
            int idx = tid + i * 128;
            int row = idx >> 2, kq = idx & 3;
            hsh[kq * 4 + 0][row] = hld[i].x;
            hsh[kq * 4 + 1][row] = hld[i].y;
            hsh[kq * 4 + 2][row] = hld[i].z;
            hsh[kq * 4 + 3][row] = hld[i].w;
        }
#pragma unroll
        for (int i = 0; i < 4; i++) {
            int idx = tid + i * 128;
            wsh[idx >> 5][idx & 31] = wld[i];
        }
        __syncthreads();

        // prefetch next chunk
        if (ch + 1 < NCH) {
            int k0 = (ch + 1) * KC;
#pragma unroll
            for (int i = 0; i < 4; i++) {
                int idx = tid + i * 128;
                int row = idx >> 2, kq = idx & 3;
                hld[i] = *reinterpret_cast<const float4*>(hs + (size_t)(rowBase + row) * HH + k0 + kq * 4);
            }
#pragma unroll
            for (int i = 0; i < 4; i++) {
                int idx = tid + i * 128;
                wld[i] = W[(k0 + (idx >> 5)) * LL + (idx & 31)];
            }
        }

        // FMA over this chunk
#pragma unroll
        for (int kk = 0; kk < KC; kk++) {
            float4 h0 = *reinterpret_cast<const float4*>(&hsh[kk][r0]);
            float4 h1 = *reinterpret_cast<const float4*>(&hsh[kk][r0 + 4]);
            float4 w0 = *reinterpret_cast<const float4*>(&wsh[kk][c0]);
            unsigned long long wp0 = pk2(w0.x, w0.y);
            unsigned long long wp1 = pk2(w0.z, w0.w);
            float hv[8] = {h0.x, h0.y, h0.z, h0.w, h1.x, h1.y, h1.z, h1.w};
#pragma unroll
            for (int r = 0; r < 8; r++) {
                unsigned long long hv2 = pk2(hv[r], hv[r]);
                acc[r][0] = f2fma(hv2, wp0, acc[r][0]);
                acc[r][1] = f2fma(hv2, wp1, acc[r][1]);
            }
        }
    }

    // epilogue: write em and exp(em)
#pragma unroll
    for (int r = 0; r < 8; r++) {
        float a[4];
        upk2(acc[r][0], a[0], a[1]);
        upk2(acc[r][1], a[2], a[3]);
        size_t base = (size_t)(rowBase + r0 + r) * LL + c0;
        *reinterpret_cast<float4*>(d_em + base) = make_float4(a[0], a[1], a[2], a[3]);
        *reinterpret_cast<float4*>(d_emx + base) =
            make_float4(__expf(a[0]), __expf(a[1]), __expf(a[2]), __expf(a[3]));
    }
}

// ============================================================
// Kernel 2: CRF per batch. 1 block/batch, 3 warps:
//   warp0: forward (linear-domain, periodic renorm) -> denom
//   warp1: Viterbi (fmax-tree + equality-mask argmax) -> hist, best_last
//   warp2: numerator (gold path score)
// then warp0: backtrace (thread0 walk + parallel zero fill)
// ============================================================
__global__ __launch_bounds__(96) void crf_k(const int* __restrict__ attn,
                                            const int* __restrict__ labels,
                                            const float* __restrict__ startT,
                                            const float* __restrict__ endT,
                                            const float* __restrict__ trans,
                                            float* __restrict__ out) {
    __shared__ unsigned char hist[TT - 1][LL];
    __shared__ float sh_denom, sh_numer;
    __shared__ int sh_best;

    const int b = blockIdx.x;
    const int tid = threadIdx.x;
    const int w = tid >> 5, lane = tid & 31;
    const float* emb = d_em + (size_t)b * TT * LL;
    const float* embx = d_emx + (size_t)b * TT * LL;
    const unsigned F = 0xffffffffu;

    // sequence length (mask is a prefix mask)
    int len = 0;
    {
        const int* am = attn + b * TT;
        for (int tt = lane; tt < TT; tt += 32) len += am[tt];
#pragma unroll
        for (int o = 16; o; o >>= 1) len += __shfl_xor_sync(F, len, o);
    }

    if (w == 0) {
        // -------- forward recursion, linear domain --------
        float Et[32];
#pragma unroll
        for (int i = 0; i < 32; i++) Et[i] = __expf(trans[i * LL + lane]);
        float sc0 = startT[lane] + emb[lane];
        float ref0 = __shfl_sync(F, sc0, 0);
        float u = __expf(sc0 - ref0);
        float c = ref0;

        float x1 = embx[LL + lane];
        float x2 = embx[2 * LL + lane];
        for (int t = 1; t < len; t++) {
            float ext = x1;
            x1 = x2;
            int tp = (t + 2 < TT) ? (t + 2) : (TT - 1);
            x2 = embx[tp * LL + lane];

            float s0 = 0.f, s1 = 0.f, s2 = 0.f, s3 = 0.f;
#pragma unroll
            for (int i = 0; i < 32; i += 4) {
                s0 = fmaf(__shfl_sync(F, u, i + 0), Et[i + 0], s0);
                s1 = fmaf(__shfl_sync(F, u, i + 1), Et[i + 1], s1);
                s2 = fmaf(__shfl_sync(F, u, i + 2), Et[i + 2], s2);
                s3 = fmaf(__shfl_sync(F, u, i + 3), Et[i + 3], s3);
            }
            u = ext * ((s0 + s1) + (s2 + s3));

            if ((t & 7) == 0) {
                float r = __shfl_sync(F, u, 0);
                u *= frcp(r);
                c += __logf(r);
            }
        }
        // denom = c + log(sum_j u_j * exp(end_j))
        float v = u * __expf(endT[lane]);
#pragma unroll
        for (int o = 16; o; o >>= 1) v += __shfl_xor_sync(F, v, o);
        if (lane == 0) sh_denom = c + __logf(v);
    } else if (w == 1) {
        // -------- Viterbi recursion --------
        float tr[32];
#pragma unroll
        for (int i = 0; i < 32; i++) tr[i] = trans[i * LL + lane];
        float vs = startT[lane] + emb[lane];
        float e1 = emb[LL + lane];
        float e2 = emb[2 * LL + lane];
        for (int t = 1; t < len; t++) {
            float emt = e1;
            e1 = e2;
            int tp = (t + 2 < TT) ? (t + 2) : (TT - 1);
            e2 = emb[tp * LL + lane];

            // candidates (exact same fp ops as reference: score_i + trans[i][j])
            float cd[32];
#pragma unroll
            for (int i = 0; i < 32; i++) cd[i] = __shfl_sync(F, vs, i) + tr[i];

            // max via fmax tree (no predicates on critical path)
            float m16[16];
#pragma unroll
            for (int i = 0; i < 16; i++) m16[i] = fmaxf(cd[2 * i], cd[2 * i + 1]);
            float m8[8];
#pragma unroll
            for (int i = 0; i < 8; i++) m8[i] = fmaxf(m16[2 * i], m16[2 * i + 1]);
            float m4[4];
#pragma unroll
            for (int i = 0; i < 4; i++) m4[i] = fmaxf(m8[2 * i], m8[2 * i + 1]);
            float best = fmaxf(fmaxf(m4[0], m4[1]), fmaxf(m4[2], m4[3]));

            // argmax index: equality mask (independent compares), lowest index wins
            unsigned mk = 0u;
#pragma unroll
            for (int i = 0; i < 32; i++) mk |= (cd[i] == best) ? (1u << i) : 0u;
            hist[t - 1][lane] = (unsigned char)(__ffs(mk) - 1);

            vs = best + emt;
        }
        // best_last = argmax_j (vs_j + end_j), first index on ties
        float v = vs + endT[lane];
        int idx = lane;
#pragma unroll
        for (int o = 16; o; o >>= 1) {
            float ov = __shfl_xor_sync(F, v, o);
            int oi = __shfl_xor_sync(F, idx, o);
            if (ov > v || (ov == v && oi < idx)) { v = ov; idx = oi; }
        }
        if (lane == 0) sh_best = idx;
    } else {
        // -------- numerator (gold path score) --------
        const int* lab = labels + b * TT;
        float part = 0.f;
        for (int t = 1 + lane; t < TT; t += 32) {
            if (t < len) {
                int lt = lab[t], lp = lab[t - 1];
                part += emb[t * LL + lt] + trans[lp * LL + lt];
            }
        }
#pragma unroll
        for (int o = 16; o; o >>= 1) part += __shfl_xor_sync(F, part, o);
        if (lane == 0) {
            int l0 = lab[0];
            int llast = lab[len - 1];
            part += startT[l0] + emb[l0] + endT[llast];
            sh_numer = part;
        }
    }
    __syncthreads();

    if (w == 0) {
        const int last_idx = len - 1;
        const int bestl = sh_best;
        float* pred = out + 1 + (size_t)b * TT;
        // parallel zero-fill for t > last_idx (PAD = 0)
        for (int tt = last_idx + 1 + lane; tt < TT; tt += 32) pred[tt] = 0.0f;
        if (lane == 0) {
            d_part[b] = sh_denom - sh_numer;
            // backtrace (hist in shared), only len steps
            pred[last_idx] = (float)bestl;
            int carry = bestl;
            for (int t = last_idx - 1; t >= 0; t--) {
                int prev = hist[t][carry];
                pred[t] = (float)prev;
                carry = prev;
            }
        }
    }
}

// ============================================================
// Kernel 3: deterministic loss reduce (no float atomics)
// ============================================================
__global__ void fin_k(float* __restrict__ out) {
    int l = threadIdx.x;
    float v = d_part[2 * l] + d_part[2 * l + 1];
#pragma unroll
    for (int o = 16; o; o >>= 1) v += __shfl_xor_sync(0xffffffffu, v, o);
    if (l == 0) out[0] = v;
}

extern "C" void kernel_launch(void* const* d_in, const int* in_sizes, int n_in,
                              void* d_out, int out_size) {
    (void)in_sizes; (void)n_in; (void)out_size;
    const float* hs     = (const float*)d_in[0];
    const int*   attn   = (const int*)d_in[1];
    const int*   labels = (const int*)d_in[2];
    const float* W      = (const float*)d_in[3];
    const float* bias   = (const float*)d_in[4];
    const float* startT = (const float*)d_in[5];
    const float* endT   = (const float*)d_in[6];
    const float* trans  = (const float*)d_in[7];
    float* out = (float*)d_out;

    gemm_k<<<(BB * TT) / 128, 128>>>(hs, W, bias);
    crf_k<<<BB, 96>>>(attn, labels, startT, endT, trans, out);
    fin_k<<<1, 32>>>(out);
}

// round 4
// speedup vs baseline: 1.4138x; 1.4138x over previous
#include <cuda_runtime.h>
#include <math.h>

#define BB 64
#define TT 512
#define HH 768
#define LL 32

// Scratch (static device globals: no allocation allowed)
__device__ float d_em[BB * TT * LL];    // emissions (log domain), 4 MB
__device__ float d_emx[BB * TT * LL];   // exp(emissions), 4 MB
__device__ float d_part[BB];            // per-batch (denom - numer)

typedef unsigned long long ull;

// ---- packed f32x2 helpers (Blackwell, PTX-only) ----
__device__ __forceinline__ ull pk2(float a, float b) {
    ull r;
    asm("mov.b64 %0, {%1, %2};" : "=l"(r) : "f"(a), "f"(b));
    return r;
}
__device__ __forceinline__ void upk2(ull v, float& a, float& b) {
    asm("mov.b64 {%0, %1}, %2;" : "=f"(a), "=f"(b) : "l"(v));
}
__device__ __forceinline__ ull f2fma(ull a, ull b, ull c) {
    ull d;
    asm("fma.rn.f32x2 %0, %1, %2, %3;" : "=l"(d) : "l"(a), "l"(b), "l"(c));
    return d;
}
__device__ __forceinline__ ull f2add(ull a, ull b) {
    ull d;
    asm("add.rn.f32x2 %0, %1, %2;" : "=l"(d) : "l"(a), "l"(b));
    return d;
}
__device__ __forceinline__ float frcp(float x) {
    float r;
    asm("rcp.approx.f32 %0, %1;" : "=f"(r) : "f"(x));
    return r;
}

// ============================================================
// Kernel 1: emissions = hidden_states @ W + b  (unchanged from R3)
// ============================================================
#define KC 16
__global__ __launch_bounds__(128) void gemm_k(const float* __restrict__ hs,
                                              const float* __restrict__ W,
                                              const float* __restrict__ bias) {
    __shared__ float hsh[KC][128];
    __shared__ float wsh[KC][32];
    const int tid = threadIdx.x;
    const int rowBase = blockIdx.x * 128;
    const int tr = tid >> 3, tc = tid & 7;
    const int r0 = tr * 8, c0 = tc * 4;

    ull acc[8][2];
    {
        float4 bb = *reinterpret_cast<const float4*>(bias + c0);
#pragma unroll
        for (int r = 0; r < 8; r++) {
            acc[r][0] = pk2(bb.x, bb.y);
            acc[r][1] = pk2(bb.z, bb.w);
        }
    }

    float4 hld[4];
    float  wld[4];

#pragma unroll
    for (int i = 0; i < 4; i++) {
        int idx = tid + i * 128;
        int row = idx >> 2, kq = idx & 3;
        hld[i] = *reinterpret_cast<const float4*>(hs + (size_t)(rowBase + row) * HH + kq * 4);
    }
#pragma unroll
    for (int i = 0; i < 4; i++) {
        int idx = tid + i * 128;
        wld[i] = W[(idx >> 5) * LL + (idx & 31)];
    }

    const int NCH = HH / KC;  // 48
    for (int ch = 0; ch < NCH; ch++) {
        __syncthreads();
#pragma unroll
        for (int i = 0; i < 4; i++) {
            int idx = tid + i * 128;
            int row = idx >> 2, kq = idx & 3;
            hsh[kq * 4 + 0][row] = hld[i].x;
            hsh[kq * 4 + 1][row] = hld[i].y;
            hsh[kq * 4 + 2][row] = hld[i].z;
            hsh[kq * 4 + 3][row] = hld[i].w;
        }
#pragma unroll
        for (int i = 0; i < 4; i++) {
            int idx = tid + i * 128;
            wsh[idx >> 5][idx & 31] = wld[i];
        }
        __syncthreads();

        if (ch + 1 < NCH) {
            int k0 = (ch + 1) * KC;
#pragma unroll
            for (int i = 0; i < 4; i++) {
                int idx = tid + i * 128;
                int row = idx >> 2, kq = idx & 3;
                hld[i] = *reinterpret_cast<const float4*>(hs + (size_t)(rowBase + row) * HH + k0 + kq * 4);
            }
#pragma unroll
            for (int i = 0; i < 4; i++) {
                int idx = tid + i * 128;
                wld[i] = W[(k0 + (idx >> 5)) * LL + (idx & 31)];
            }
        }

#pragma unroll
        for (int kk = 0; kk < KC; kk++) {
            float4 h0 = *reinterpret_cast<const float4*>(&hsh[kk][r0]);
            float4 h1 = *reinterpret_cast<const float4*>(&hsh[kk][r0 + 4]);
            float4 w0 = *reinterpret_cast<const float4*>(&wsh[kk][c0]);
            ull wp0 = pk2(w0.x, w0.y);
            ull wp1 = pk2(w0.z, w0.w);
            float hv[8] = {h0.x, h0.y, h0.z, h0.w, h1.x, h1.y, h1.z, h1.w};
#pragma unroll
            for (int r = 0; r < 8; r++) {
                ull hv2 = pk2(hv[r], hv[r]);
                acc[r][0] = f2fma(hv2, wp0, acc[r][0]);
                acc[r][1] = f2fma(hv2, wp1, acc[r][1]);
            }
        }
    }

#pragma unroll
    for (int r = 0; r < 8; r++) {
        float a[4];
        upk2(acc[r][0], a[0], a[1]);
        upk2(acc[r][1], a[2], a[3]);
        size_t base = (size_t)(rowBase + r0 + r) * LL + c0;
        *reinterpret_cast<float4*>(d_em + base) = make_float4(a[0], a[1], a[2], a[3]);
        *reinterpret_cast<float4*>(d_emx + base) =
            make_float4(__expf(a[0]), __expf(a[1]), __expf(a[2]), __expf(a[3]));
    }
}

// ============================================================
// Kernel 2: CRF per batch. 1 block/batch, 3 warps.
// Dynamic smem layout (floats):
//   bestv [512][32]   : Viterbi max value per (t, j), t=1..len-1
//   vsAll [512][32]   : Viterbi scores vs(t) (precomputed post-mainloop)
//   trS   [32][33]    : transitions, padded (conflict-free column reads)
//   vshF  [2][32]     : forward broadcast double buffer
//   vshV  [2][32]     : viterbi broadcast double buffer
// ============================================================
#define OFF_BESTV 0
#define OFF_VSALL (512 * 32)
#define OFF_TRS   (2 * 512 * 32)
#define OFF_VSHF  (2 * 512 * 32 + 32 * 33)
#define OFF_VSHV  (OFF_VSHF + 64)
#define CRF_SMEM_FLOATS (OFF_VSHV + 64)

__global__ __launch_bounds__(96) void crf_k(const int* __restrict__ attn,
                                            const int* __restrict__ labels,
                                            const float* __restrict__ startT,
                                            const float* __restrict__ endT,
                                            const float* __restrict__ trans,
                                            float* __restrict__ out) {
    extern __shared__ float sm[];
    float* bestv = sm + OFF_BESTV;
    float* vsAll = sm + OFF_VSALL;
    float* trS   = sm + OFF_TRS;
    float* vshF  = sm + OFF_VSHF;
    float* vshV  = sm + OFF_VSHV;
    __shared__ float sh_denom, sh_numer;
    __shared__ int sh_best;

    const int b = blockIdx.x;
    const int tid = threadIdx.x;
    const int w = tid >> 5, lane = tid & 31;
    const float* emb = d_em + (size_t)b * TT * LL;
    const float* embx = d_emx + (size_t)b * TT * LL;
    const unsigned F = 0xffffffffu;

    // transitions into padded smem (used by backtrace)
    for (int idx = tid; idx < LL * LL; idx += 96)
        trS[(idx >> 5) * 33 + (idx & 31)] = trans[idx];

    // sequence length (prefix mask)
    int len = 0;
    {
        const int* am = attn + b * TT;
        for (int tt = lane; tt < TT; tt += 32) len += am[tt];
#pragma unroll
        for (int o = 16; o; o >>= 1) len += __shfl_xor_sync(F, len, o);
    }

    if (w == 0) {
        // -------- forward recursion, linear domain, smem broadcast + FFMA2 ----
        ull Et2[16];
#pragma unroll
        for (int q = 0; q < 16; q++)
            Et2[q] = pk2(__expf(trans[(2 * q) * LL + lane]),
                         __expf(trans[(2 * q + 1) * LL + lane]));
        float sc0 = startT[lane] + emb[lane];
        float ref0 = __shfl_sync(F, sc0, 0);
        float u = __expf(sc0 - ref0);
        float c = ref0;

        vshF[lane] = u;
        __syncwarp();

        float x1 = embx[LL + lane];
        float x2 = embx[2 * LL + lane];
        for (int t = 1; t < len; t++) {
            float ext = x1;
            x1 = x2;
            int tp = (t + 2 < TT) ? (t + 2) : (TT - 1);
            x2 = embx[tp * LL + lane];

            const ulonglong2* u2p =
                reinterpret_cast<const ulonglong2*>(&vshF[((t - 1) & 1) * 32]);
            ull s0 = 0, s1 = 0, s2 = 0, s3 = 0;
#pragma unroll
            for (int q = 0; q < 8; q += 2) {
                ulonglong2 ua = u2p[q];
                ulonglong2 ub = u2p[q + 1];
                s0 = f2fma(ua.x, Et2[2 * q], s0);
                s1 = f2fma(ua.y, Et2[2 * q + 1], s1);
                s2 = f2fma(ub.x, Et2[2 * q + 2], s2);
                s3 = f2fma(ub.y, Et2[2 * q + 3], s3);
            }
            float a0, a1, a2, a3, a4, a5, a6, a7;
            upk2(s0, a0, a1); upk2(s1, a2, a3);
            upk2(s2, a4, a5); upk2(s3, a6, a7);
            u = ext * (((a0 + a1) + (a2 + a3)) + ((a4 + a5) + (a6 + a7)));

            if ((t & 7) == 0) {
                float r = __shfl_sync(F, u, 0);
                u *= frcp(r);
                c += __logf(r);
            }
            vshF[(t & 1) * 32 + lane] = u;
            __syncwarp();
        }
        float v = u * __expf(endT[lane]);
#pragma unroll
        for (int o = 16; o; o >>= 1) v += __shfl_xor_sync(F, v, o);
        if (lane == 0) sh_denom = c + __logf(v);
    } else if (w == 1) {
        // -------- Viterbi: max only (argmax deferred to backtrace) --------
        ull tr2[16];
#pragma unroll
        for (int q = 0; q < 16; q++)
            tr2[q] = pk2(trans[(2 * q) * LL + lane], trans[(2 * q + 1) * LL + lane]);
        float vs = startT[lane] + emb[lane];
        vshV[lane] = vs;
        __syncwarp();

        float e1 = emb[LL + lane];
        float e2 = emb[2 * LL + lane];
        for (int t = 1; t < len; t++) {
            float emt = e1;
            e1 = e2;
            int tp = (t + 2 < TT) ? (t + 2) : (TT - 1);
            e2 = emb[tp * LL + lane];

            const ulonglong2* v2p =
                reinterpret_cast<const ulonglong2*>(&vshV[((t - 1) & 1) * 32]);
            float m0 = -3.0e38f, m1 = -3.0e38f, m2 = -3.0e38f, m3 = -3.0e38f;
#pragma unroll
            for (int q = 0; q < 8; q++) {
                ulonglong2 uu = v2p[q];
                ull c01 = f2add(uu.x, tr2[2 * q]);
                ull c23 = f2add(uu.y, tr2[2 * q + 1]);
                float c0, c1, c2, c3;
                upk2(c01, c0, c1);
                upk2(c23, c2, c3);
                m0 = fmaxf(m0, c0);
                m1 = fmaxf(m1, c1);
                m2 = fmaxf(m2, c2);
                m3 = fmaxf(m3, c3);
            }
            float best = fmaxf(fmaxf(m0, m1), fmaxf(m2, m3));
            bestv[t * 32 + lane] = best;
            vs = best + emt;
            vshV[(t & 1) * 32 + lane] = vs;
            __syncwarp();
        }
        float v = vs + endT[lane];
        int idx = lane;
#pragma unroll
        for (int o = 16; o; o >>= 1) {
            float ov = __shfl_xor_sync(F, v, o);
            int oi = __shfl_xor_sync(F, idx, o);
            if (ov > v || (ov == v && oi < idx)) { v = ov; idx = oi; }
        }
        if (lane == 0) sh_best = idx;
    } else {
        // -------- numerator (gold path score) --------
        const int* lab = labels + b * TT;
        float part = 0.f;
        for (int t = 1 + lane; t < TT; t += 32) {
            if (t < len) {
                int lt = lab[t], lp = lab[t - 1];
                part += emb[t * LL + lt] + trans[lp * LL + lt];
            }
        }
#pragma unroll
        for (int o = 16; o; o >>= 1) part += __shfl_xor_sync(F, part, o);
        if (lane == 0) {
            int l0 = lab[0];
            int llast = lab[len - 1];
            part += startT[l0] + emb[l0] + endT[llast];
            sh_numer = part;
        }
    }
    __syncthreads();

    // -------- cooperative precompute: vsAll[t][i] = vs_i(t) (bit-exact) -----
    for (int idx = tid; idx < len * 32; idx += 96) {
        int t = idx >> 5, i = idx & 31;
        float e = emb[idx];
        vsAll[idx] = ((t == 0) ? startT[i] : bestv[idx]) + e;
    }
    __syncthreads();

    if (w == 0) {
        const int last_idx = len - 1;
        const int bestl = sh_best;
        float* pred = out + 1 + (size_t)b * TT;
        for (int tt = last_idx + 1 + lane; tt < TT; tt += 32) pred[tt] = 0.0f;
        if (lane == 0) {
            d_part[b] = sh_denom - sh_numer;
            pred[last_idx] = (float)bestl;
        }
        // -------- warp-parallel backtrace via exact value matching --------
        int carry = bestl;
        const float trv_base = 0.0f; (void)trv_base;
        for (int t = last_idx; t >= 1; t--) {
            float vsp = vsAll[(t - 1) * 32 + lane];
            float trv = trS[lane * 33 + carry];
            float tgt = bestv[t * 32 + carry];
            unsigned mk = __ballot_sync(F, (vsp + trv) == tgt);
            int prev = __ffs(mk) - 1;
            if (lane == 0) pred[t - 1] = (float)prev;
            carry = prev;
        }
    }
}

// ============================================================
// Kernel 3: deterministic loss reduce (no float atomics)
// ============================================================
__global__ void fin_k(float* __restrict__ out) {
    int l = threadIdx.x;
    float v = d_part[2 * l] + d_part[2 * l + 1];
#pragma unroll
    for (int o = 16; o; o >>= 1) v += __shfl_xor_sync(0xffffffffu, v, o);
    if (l == 0) out[0] = v;
}

extern "C" void kernel_launch(void* const* d_in, const int* in_sizes, int n_in,
                              void* d_out, int out_size) {
    (void)in_sizes; (void)n_in; (void)out_size;
    const float* hs     = (const float*)d_in[0];
    const int*   attn   = (const int*)d_in[1];
    const int*   labels = (const int*)d_in[2];
    const float* W      = (const float*)d_in[3];
    const float* bias   = (const float*)d_in[4];
    const float* startT = (const float*)d_in[5];
    const float* endT   = (const float*)d_in[6];
    const float* trans  = (const float*)d_in[7];
    float* out = (float*)d_out;

    const int crf_smem = CRF_SMEM_FLOATS * sizeof(float);  // ~136 KB
    cudaFuncSetAttribute(crf_k, cudaFuncAttributeMaxDynamicSharedMemorySize, crf_smem);

    gemm_k<<<(BB * TT) / 128, 128>>>(hs, W, bias);
    crf_k<<<BB, 96, crf_smem>>>(attn, labels, startT, endT, trans, out);
    fin_k<<<1, 32>>>(out);
}

// round 5
// speedup vs baseline: 1.6552x; 1.1707x over previous
#include <cuda_runtime.h>
#include <math.h>

#define BB 64
#define TT 512
#define HH 768
#define LL 32

// Scratch (static device globals: no allocation allowed)
__device__ float d_em[BB * TT * LL];    // emissions (log domain), 4 MB
__device__ float d_part[BB];            // per-batch (denom - numer)

typedef unsigned long long ull;

// ---- packed f32x2 helpers (Blackwell, PTX-only) ----
__device__ __forceinline__ ull pk2(float a, float b) {
    ull r;
    asm("mov.b64 %0, {%1, %2};" : "=l"(r) : "f"(a), "f"(b));
    return r;
}
__device__ __forceinline__ void upk2(ull v, float& a, float& b) {
    asm("mov.b64 {%0, %1}, %2;" : "=f"(a), "=f"(b) : "l"(v));
}
__device__ __forceinline__ ull f2fma(ull a, ull b, ull c) {
    ull d;
    asm("fma.rn.f32x2 %0, %1, %2, %3;" : "=l"(d) : "l"(a), "l"(b), "l"(c));
    return d;
}
__device__ __forceinline__ ull f2add(ull a, ull b) {
    ull d;
    asm("add.rn.f32x2 %0, %1, %2;" : "=l"(d) : "l"(a), "l"(b));
    return d;
}
__device__ __forceinline__ float frcp(float x) {
    float r;
    asm("rcp.approx.f32 %0, %1;" : "=f"(r) : "f"(x));
    return r;
}

// ============================================================
// Kernel 1: emissions = hidden_states @ W + b
// (R3 structure; epilogue writes only d_em now)
// ============================================================
#define KC 16
__global__ __launch_bounds__(128) void gemm_k(const float* __restrict__ hs,
                                              const float* __restrict__ W,
                                              const float* __restrict__ bias) {
    __shared__ float hsh[KC][128];
    __shared__ float wsh[KC][32];
    const int tid = threadIdx.x;
    const int rowBase = blockIdx.x * 128;
    const int tr = tid >> 3, tc = tid & 7;
    const int r0 = tr * 8, c0 = tc * 4;

    ull acc[8][2];
    {
        float4 bb = *reinterpret_cast<const float4*>(bias + c0);
#pragma unroll
        for (int r = 0; r < 8; r++) {
            acc[r][0] = pk2(bb.x, bb.y);
            acc[r][1] = pk2(bb.z, bb.w);
        }
    }

    float4 hld[4];
    float  wld[4];

#pragma unroll
    for (int i = 0; i < 4; i++) {
        int idx = tid + i * 128;
        int row = idx >> 2, kq = idx & 3;
        hld[i] = *reinterpret_cast<const float4*>(hs + (size_t)(rowBase + row) * HH + kq * 4);
    }
#pragma unroll
    for (int i = 0; i < 4; i++) {
        int idx = tid + i * 128;
        wld[i] = W[(idx >> 5) * LL + (idx & 31)];
    }

    const int NCH = HH / KC;  // 48
    for (int ch = 0; ch < NCH; ch++) {
        __syncthreads();
#pragma unroll
        for (int i = 0; i < 4; i++) {
            int idx = tid + i * 128;
            int row = idx >> 2, kq = idx & 3;
            hsh[kq * 4 + 0][row] = hld[i].x;
            hsh[kq * 4 + 1][row] = hld[i].y;
            hsh[kq * 4 + 2][row] = hld[i].z;
            hsh[kq * 4 + 3][row] = hld[i].w;
        }
#pragma unroll
        for (int i = 0; i < 4; i++) {
            int idx = tid + i * 128;
            wsh[idx >> 5][idx & 31] = wld[i];
        }
        __syncthreads();

        if (ch + 1 < NCH) {
            int k0 = (ch + 1) * KC;
#pragma unroll
            for (int i = 0; i < 4; i++) {
                int idx = tid + i * 128;
                int row = idx >> 2, kq = idx & 3;
                hld[i] = *reinterpret_cast<const float4*>(hs + (size_t)(rowBase + row) * HH + k0 + kq * 4);
            }
#pragma unroll
            for (int i = 0; i < 4; i++) {
                int idx = tid + i * 128;
                wld[i] = W[(k0 + (idx >> 5)) * LL + (idx & 31)];
            }
        }

#pragma unroll
        for (int kk = 0; kk < KC; kk++) {
            float4 h0 = *reinterpret_cast<const float4*>(&hsh[kk][r0]);
            float4 h1 = *reinterpret_cast<const float4*>(&hsh[kk][r0 + 4]);
            float4 w0 = *reinterpret_cast<const float4*>(&wsh[kk][c0]);
            ull wp0 = pk2(w0.x, w0.y);
            ull wp1 = pk2(w0.z, w0.w);
            float hv[8] = {h0.x, h0.y, h0.z, h0.w, h1.x, h1.y, h1.z, h1.w};
#pragma unroll
            for (int r = 0; r < 8; r++) {
                ull hv2 = pk2(hv[r], hv[r]);
                acc[r][0] = f2fma(hv2, wp0, acc[r][0]);
                acc[r][1] = f2fma(hv2, wp1, acc[r][1]);
            }
        }
    }

#pragma unroll
    for (int r = 0; r < 8; r++) {
        float a[4];
        upk2(acc[r][0], a[0], a[1]);
        upk2(acc[r][1], a[2], a[3]);
        size_t base = (size_t)(rowBase + r0 + r) * LL + c0;
        *reinterpret_cast<float4*>(d_em + base) = make_float4(a[0], a[1], a[2], a[3]);
    }
}

// ============================================================
// Kernel 2: CRF per batch. 1 block/batch, 3 warps.
// All recursion state in shared memory (no gmem in the loops).
// Dynamic smem layout (floats):
//   emS   [512][32] : emissions for this batch (preloaded)
//   bestv [512][32] : Viterbi max value per (t, j), t=1..len-1
//   trS   [32][33]  : transitions, padded
//   vshF  [2][32]   : forward broadcast double buffer
//   vshV  [2][32]   : viterbi broadcast double buffer
// ============================================================
#define OFF_EMS   0
#define OFF_BESTV (512 * 32)
#define OFF_TRS   (2 * 512 * 32)
#define OFF_VSHF  (2 * 512 * 32 + 32 * 33)
#define OFF_VSHV  (OFF_VSHF + 64)
#define CRF_SMEM_FLOATS (OFF_VSHV + 64)

__global__ __launch_bounds__(96) void crf_k(const int* __restrict__ attn,
                                            const int* __restrict__ labels,
                                            const float* __restrict__ startT,
                                            const float* __restrict__ endT,
                                            const float* __restrict__ trans,
                                            float* __restrict__ out) {
    extern __shared__ float sm[];
    float* emS   = sm + OFF_EMS;
    float* bestv = sm + OFF_BESTV;
    float* trS   = sm + OFF_TRS;
    float* vshF  = sm + OFF_VSHF;
    float* vshV  = sm + OFF_VSHV;
    __shared__ float sh_denom, sh_numer;
    __shared__ int sh_best;

    const int b = blockIdx.x;
    const int tid = threadIdx.x;
    const int w = tid >> 5, lane = tid & 31;
    const unsigned F = 0xffffffffu;

    // ---- preload emissions tile (64 KB) + transitions ----
    {
        const float4* src = reinterpret_cast<const float4*>(d_em + (size_t)b * TT * LL);
        float4* dst = reinterpret_cast<float4*>(emS);
#pragma unroll 4
        for (int i = tid; i < TT * LL / 4; i += 96) dst[i] = src[i];
        for (int idx = tid; idx < LL * LL; idx += 96)
            trS[(idx >> 5) * 33 + (idx & 31)] = trans[idx];
    }

    // sequence length (prefix mask)
    int len = 0;
    {
        const int* am = attn + b * TT;
        for (int tt = lane; tt < TT; tt += 32) len += am[tt];
#pragma unroll
        for (int o = 16; o; o >>= 1) len += __shfl_xor_sync(F, len, o);
    }
    __syncthreads();

    if (w == 0) {
        // -------- forward recursion, linear domain, smem broadcast + FFMA2 ----
        ull Et2[16];
#pragma unroll
        for (int q = 0; q < 16; q++)
            Et2[q] = pk2(__expf(trans[(2 * q) * LL + lane]),
                         __expf(trans[(2 * q + 1) * LL + lane]));
        float sc0 = startT[lane] + emS[lane];
        float ref0 = __shfl_sync(F, sc0, 0);
        float u = __expf(sc0 - ref0);
        float c = ref0;

        vshF[lane] = u;
        __syncwarp();

        for (int t = 1; t < len; t++) {
            float ext = __expf(emS[t * 32 + lane]);   // LDS+MUFU off critical path

            const ulonglong2* u2p =
                reinterpret_cast<const ulonglong2*>(&vshF[((t - 1) & 1) * 32]);
            ull s0 = 0, s1 = 0, s2 = 0, s3 = 0;
#pragma unroll
            for (int q = 0; q < 8; q += 2) {
                ulonglong2 ua = u2p[q];
                ulonglong2 ub = u2p[q + 1];
                s0 = f2fma(ua.x, Et2[2 * q], s0);
                s1 = f2fma(ua.y, Et2[2 * q + 1], s1);
                s2 = f2fma(ub.x, Et2[2 * q + 2], s2);
                s3 = f2fma(ub.y, Et2[2 * q + 3], s3);
            }
            float a0, a1, a2, a3, a4, a5, a6, a7;
            upk2(s0, a0, a1); upk2(s1, a2, a3);
            upk2(s2, a4, a5); upk2(s3, a6, a7);
            u = ext * (((a0 + a1) + (a2 + a3)) + ((a4 + a5) + (a6 + a7)));

            if ((t & 7) == 0) {
                float r = __shfl_sync(F, u, 0);
                u *= frcp(r);
                c += __logf(r);
            }
            vshF[(t & 1) * 32 + lane] = u;
            __syncwarp();
        }
        float v = u * __expf(endT[lane]);
#pragma unroll
        for (int o = 16; o; o >>= 1) v += __shfl_xor_sync(F, v, o);
        if (lane == 0) sh_denom = c + __logf(v);
    } else if (w == 1) {
        // -------- Viterbi: max only (argmax deferred to backtrace) --------
        ull tr2[16];
#pragma unroll
        for (int q = 0; q < 16; q++)
            tr2[q] = pk2(trans[(2 * q) * LL + lane], trans[(2 * q + 1) * LL + lane]);
        float vs = startT[lane] + emS[lane];
        vshV[lane] = vs;
        __syncwarp();

        for (int t = 1; t < len; t++) {
            float emt = emS[t * 32 + lane];

            const ulonglong2* v2p =
                reinterpret_cast<const ulonglong2*>(&vshV[((t - 1) & 1) * 32]);
            float m0 = -3.0e38f, m1 = -3.0e38f, m2 = -3.0e38f, m3 = -3.0e38f;
#pragma unroll
            for (int q = 0; q < 8; q++) {
                ulonglong2 uu = v2p[q];
                ull c01 = f2add(uu.x, tr2[2 * q]);
                ull c23 = f2add(uu.y, tr2[2 * q + 1]);
                float c0, c1, c2, c3;
                upk2(c01, c0, c1);
                upk2(c23, c2, c3);
                m0 = fmaxf(m0, c0);
                m1 = fmaxf(m1, c1);
                m2 = fmaxf(m2, c2);
                m3 = fmaxf(m3, c3);
            }
            float best = fmaxf(fmaxf(m0, m1), fmaxf(m2, m3));
            bestv[t * 32 + lane] = best;
            vs = best + emt;
            vshV[(t & 1) * 32 + lane] = vs;
            __syncwarp();
        }
        float v = vs + endT[lane];
        int idx = lane;
#pragma unroll
        for (int o = 16; o; o >>= 1) {
            float ov = __shfl_xor_sync(F, v, o);
            int oi = __shfl_xor_sync(F, idx, o);
            if (ov > v || (ov == v && oi < idx)) { v = ov; idx = oi; }
        }
        if (lane == 0) sh_best = idx;
    } else {
        // -------- numerator (gold path score), all smem --------
        const int* lab = labels + b * TT;
        float part = 0.f;
        for (int t = 1 + lane; t < TT; t += 32) {
            if (t < len) {
                int lt = lab[t], lp = lab[t - 1];
                part += emS[t * 32 + lt] + trS[lp * 33 + lt];
            }
        }
#pragma unroll
        for (int o = 16; o; o >>= 1) part += __shfl_xor_sync(F, part, o);
        if (lane == 0) {
            int l0 = lab[0];
            int llast = lab[len - 1];
            part += startT[l0] + emS[l0] + endT[llast];
            sh_numer = part;
        }
    }
    __syncthreads();

    if (w == 0) {
        const int last_idx = len - 1;
        const int bestl = sh_best;
        float* pred = out + 1 + (size_t)b * TT;
        for (int tt = last_idx + 1 + lane; tt < TT; tt += 32) pred[tt] = 0.0f;
        if (lane == 0) {
            d_part[b] = sh_denom - sh_numer;
            pred[last_idx] = (float)bestl;
        }
        // ---- warp-parallel backtrace via exact value matching ----
        // vsp(t-1) recomputed bit-exact from bestv/startT + emS;
        // carry-independent loads pipelined one iteration ahead.
        int carry = bestl;
        float st_l = startT[lane];
        float vsp_next = ((last_idx - 1 == 0) ? st_l
                                              : bestv[(last_idx - 1) * 32 + lane]) +
                         emS[(last_idx - 1) * 32 + lane];
        for (int t = last_idx; t >= 1; t--) {
            float vsp = vsp_next;
            if (t >= 2) {
                int tm2 = t - 2;
                vsp_next = ((tm2 == 0) ? st_l : bestv[tm2 * 32 + lane]) +
                           emS[tm2 * 32 + lane];
            }
            float trv = trS[lane * 33 + carry];
            float tgt = bestv[t * 32 + carry];
            unsigned mk = __ballot_sync(F, (vsp + trv) == tgt);
            int prev = __ffs(mk) - 1;
            if (lane == 0) pred[t - 1] = (float)prev;
            carry = prev;
        }
    }
}

// ============================================================
// Kernel 3: deterministic loss reduce (no float atomics)
// ============================================================
__global__ void fin_k(float* __restrict__ out) {
    int l = threadIdx.x;
    float v = d_part[2 * l] + d_part[2 * l + 1];
#pragma unroll
    for (int o = 16; o; o >>= 1) v += __shfl_xor_sync(0xffffffffu, v, o);
    if (l == 0) out[0] = v;
}

extern "C" void kernel_launch(void* const* d_in, const int* in_sizes, int n_in,
                              void* d_out, int out_size) {
    (void)in_sizes; (void)n_in; (void)out_size;
    const float* hs     = (const float*)d_in[0];
    const int*   attn   = (const int*)d_in[1];
    const int*   labels = (const int*)d_in[2];
    const float* W      = (const float*)d_in[3];
    const float* bias   = (const float*)d_in[4];
    const float* startT = (const float*)d_in[5];
    const float* endT   = (const float*)d_in[6];
    const float* trans  = (const float*)d_in[7];
    float* out = (float*)d_out;

    const int crf_smem = CRF_SMEM_FLOATS * sizeof(float);  // ~136 KB
    cudaFuncSetAttribute(crf_k, cudaFuncAttributeMaxDynamicSharedMemorySize, crf_smem);

    gemm_k<<<(BB * TT) / 128, 128>>>(hs, W, bias);
    crf_k<<<BB, 96, crf_smem>>>(attn, labels, startT, endT, trans, out);
    fin_k<<<1, 32>>>(out);
}